// round 13
// baseline (speedup 1.0000x reference)
#include <cuda_runtime.h>
#include <cuda_fp16.h>
#include <cstdint>

#define N_NODES 50000
#define N_EDGES 800000
#define C 128
#define KCHEB 6
#define NB_SCAN ((N_NODES + 1023) / 1024)
#define NTILES ((N_NODES + 127) / 128)
#define NBLK_E ((N_EDGES + 255) / 256)
#define SPMV_SMEM_EDGES 1024

// ---------------- scratch (device globals: no allocation allowed) ----------------
// g_deg, g_cnt, g_maxkey, g_part are zero at load; the GEMM kernel re-zeros them
// at the end of every launch sequence (self-cleaning), so each replay sees zeros.
__device__ float    g_deg[N_NODES];
__device__ int      g_cnt[N_NODES];
__device__ int      g_rowptr[N_NODES + 1];
__device__ int      g_next[N_NODES];
__device__ int      g_part[NB_SCAN];             // block totals +1 sentinel
__device__ int2     g_csr[N_EDGES];              // {recv, weight bits}
__device__ __half   g_T16[KCHEB][N_NODES * C];   // T0..T5 in fp16
__device__ __half   g_WT16[KCHEB * C * C];       // WT16[k][n][cin] = W[k][cin][n]
__device__ unsigned g_maxkey;
__device__ float    g_bsum[C];                   // sum_k b_dense[k] + bias

// ---------------- helpers ----------------
__device__ __forceinline__ unsigned fkey(float f) {
    unsigned u = __float_as_uint(f);
    return (u & 0x80000000u) ? ~u : (u | 0x80000000u);
}
__device__ __forceinline__ float funkey(unsigned k) {
    return (k & 0x80000000u) ? __uint_as_float(k & 0x7fffffffu) : __uint_as_float(~k);
}

__device__ __forceinline__ void blockMaxKey(unsigned k) {
    int lane = threadIdx.x & 31, wid = threadIdx.x >> 5;
    #pragma unroll
    for (int o = 16; o > 0; o >>= 1) {
        unsigned x = __shfl_down_sync(0xffffffffu, k, o);
        k = k > x ? k : x;
    }
    __shared__ unsigned sm[32];
    if (lane == 0) sm[wid] = k;
    __syncthreads();
    if (wid == 0) {
        int nw = (blockDim.x + 31) >> 5;
        k = (lane < nw) ? sm[lane] : 0u;
        #pragma unroll
        for (int o = 16; o > 0; o >>= 1) {
            unsigned x = __shfl_down_sync(0xffffffffu, k, o);
            k = k > x ? k : x;
        }
        if (lane == 0) atomicMax(&g_maxkey, k);
    }
}

__device__ __forceinline__ void mma_f16(float* c, uint32_t a0, uint32_t a1,
                                        uint32_t a2, uint32_t a3,
                                        uint32_t b0, uint32_t b1) {
    asm volatile(
        "mma.sync.aligned.m16n8k16.row.col.f32.f16.f16.f32 "
        "{%0,%1,%2,%3}, {%4,%5,%6,%7}, {%8,%9}, {%0,%1,%2,%3};"
        : "+f"(c[0]), "+f"(c[1]), "+f"(c[2]), "+f"(c[3])
        : "r"(a0), "r"(a1), "r"(a2), "r"(a3), "r"(b0), "r"(b1));
}

__device__ __forceinline__ uint32_t smem_u32(const void* p) {
    uint32_t a;
    asm("{ .reg .u64 t; cvta.to.shared.u64 t, %1; cvt.u32.u64 %0, t; }" : "=r"(a) : "l"(p));
    return a;
}

// ---- packed f32x2 helpers (Blackwell FFMA2 path, PTX-only) ----
__device__ __forceinline__ uint64_t f32x2_bcast(float w) {
    uint64_t r;
    asm("mov.b64 %0, {%1, %1};" : "=l"(r) : "f"(w));
    return r;
}
__device__ __forceinline__ uint64_t h2_to_f32x2(uint32_t h2) {
    float2 f = __half22float2(*(__half2*)&h2);
    uint64_t r;
    asm("mov.b64 %0, {%1, %2};" : "=l"(r) : "f"(f.x), "f"(f.y));
    return r;
}
__device__ __forceinline__ void fma_f32x2(uint64_t& acc, uint64_t x, uint64_t w2) {
    asm("fma.rn.f32x2 %0, %1, %2, %0;" : "+l"(acc) : "l"(x), "l"(w2));
}
__device__ __forceinline__ float2 f32x2_unpack(uint64_t v) {
    float2 f;
    asm("mov.b64 {%0, %1}, %2;" : "=f"(f.x), "=f"(f.y) : "l"(v));
    return f;
}

#define CP_ASYNC16(dst, src, sz) \
    asm volatile("cp.async.cg.shared.global [%0], [%1], 16, %2;" \
        :: "r"(dst), "l"(src), "r"(sz) : "memory")
#define CP_COMMIT() asm volatile("cp.async.commit_group;" ::: "memory")
#define CP_WAIT0()  asm volatile("cp.async.wait_group 0;" ::: "memory")

// -------- merged setup + edge stats (deg/cnt/maxkey pre-zeroed by cleanup) -------
__global__ void k_init_stats(const float* __restrict__ nodes, const float* __restrict__ edges,
                             const int* __restrict__ senders, const float* __restrict__ W,
                             const float* __restrict__ bd, const float* __restrict__ bias) {
    unsigned i = blockIdx.x * blockDim.x + threadIdx.x;
    if (i < (unsigned)(N_NODES * C / 2)) {
        float2 f = *(const float2*)(nodes + (size_t)i * 2);
        *(__half2*)&g_T16[0][(size_t)i * 2] = __floats2half2_rn(f.x, f.y);
    }
    if (i < (unsigned)(KCHEB * C * C)) {
        unsigned kc = i >> 14, rem = i & 16383;
        unsigned n = rem >> 7, k = rem & 127;
        g_WT16[i] = __float2half(W[kc * C * C + k * C + n]);
    }
    if (i < C) {
        float s = bias[i];
        #pragma unroll
        for (int k = 0; k < KCHEB; k++) s += bd[k * C + i];
        g_bsum[i] = s;
    }
    if (blockIdx.x < NBLK_E) {
        unsigned key = 0u;
        if (i < N_EDGES) {
            float w = edges[i];
            int s = senders[i];
            atomicAdd(&g_deg[s], w);
            atomicAdd(&g_cnt[s], 1);
            key = fkey(-w);
        }
        blockMaxKey(key);
    }
}

// -------- single-pass scan (49 co-resident blocks, sentinel lookback) + deg max --
__global__ __launch_bounds__(1024) void k_scan() {
    int t = threadIdx.x;
    int b = blockIdx.x;
    int i = b * 1024 + t;
    int v = (i < N_NODES) ? g_cnt[i] : 0;
    unsigned dkey = (i < N_NODES) ? fkey(g_deg[i]) : 0u;
    int lane = t & 31, wid = t >> 5;
    int incl = v;
    #pragma unroll
    for (int o = 1; o < 32; o <<= 1) {
        int n = __shfl_up_sync(0xffffffffu, incl, o);
        if (lane >= o) incl += n;
    }
    __shared__ int ws[32];
    if (lane == 31) ws[wid] = incl;
    __syncthreads();
    if (wid == 0) {
        int x = ws[lane];
        int ix = x;
        #pragma unroll
        for (int o = 1; o < 32; o <<= 1) {
            int n = __shfl_up_sync(0xffffffffu, ix, o);
            if (lane >= o) ix += n;
        }
        ws[lane] = ix - x;
    }
    __syncthreads();
    int excl = incl - v + ws[wid];

    // publish this block's total (+1 sentinel; g_part pre-zeroed by cleanup)
    if (t == 1023) atomicExch(&g_part[b], excl + v + 1);

    // parallel wait for all predecessor totals
    __shared__ int psum[64];
    __shared__ int pre_sh;
    if (t < b) {
        int val;
        do { val = *(volatile int*)&g_part[t]; } while (val == 0);
        psum[t] = val - 1;
    }
    __syncthreads();
    if (t == 0) {
        int s = 0;
        for (int p = 0; p < b; p++) s += psum[p];
        pre_sh = s;
    }
    __syncthreads();

    int rp = excl + pre_sh;
    if (i < N_NODES) { g_rowptr[i] = rp; g_next[i] = rp; }
    if (b == NB_SCAN - 1 && t == 1023) g_rowptr[N_NODES] = rp + v;

    blockMaxKey(dkey);
}

__global__ void k_fill(const int* __restrict__ senders, const int* __restrict__ receivers,
                       const float* __restrict__ edges) {
    int e = blockIdx.x * blockDim.x + threadIdx.x;
    if (e < N_EDGES) {
        int s = senders[e];
        int p = atomicAdd(&g_next[s], 1);
        g_csr[p] = make_int2(receivers[e], __float_as_int(edges[e]));
    }
}

// ---------------- fused fp16 Laplacian matvec + Chebyshev combine ----------------
// half-warp per node; lane covers 8 halfs (uint4); 2-edge unroll; f32x2 packed FMA.
// Block's contiguous CSR slice staged in smem: dependent CSR load becomes LDS,
// cutting the per-iteration L2 latency chain roughly in half.
__global__ __launch_bounds__(256) void k_spmv16(int in_s, int prev_s, int out_s, int mode) {
    __shared__ int2 scsr[SPMV_SMEM_EDGES];

    const __half* x = g_T16[in_s];
    const __half* prev = g_T16[prev_s];
    __half* o = g_T16[out_s];

    int n0 = blockIdx.x * 16;
    int node = n0 + (threadIdx.x >> 4);
    int l = threadIdx.x & 15;

    int n0c = n0 < N_NODES ? n0 : N_NODES;
    int n1c = n0 + 16 < N_NODES ? n0 + 16 : N_NODES;
    int bbeg = g_rowptr[n0c];
    int bend = g_rowptr[n1c];
    int stot = bend - bbeg;
    if (stot > SPMV_SMEM_EDGES) stot = SPMV_SMEM_EDGES;

    // cooperative stage of the block's CSR slice (coalesced 8B loads)
    for (int i = threadIdx.x; i < stot; i += 256)
        scsr[i] = g_csr[bbeg + i];
    __syncthreads();

    if (node >= N_NODES) return;

    int beg = g_rowptr[node], end = g_rowptr[node + 1];
    int lim = bbeg + SPMV_SMEM_EDGES;   // entries below this index are in smem
    int c8 = l * 8;
    uint64_t A0 = 0ull, A1 = 0ull, A2 = 0ull, A3 = 0ull;  // packed {f32,f32} accumulators

    int e = beg;
    for (; e + 2 <= end; e += 2) {
        int2 e0 = (e     < lim) ? scsr[e - bbeg]     : g_csr[e];
        int2 e1 = (e + 1 < lim) ? scsr[e + 1 - bbeg] : g_csr[e + 1];
        uint64_t w0 = f32x2_bcast(__int_as_float(e0.y));
        uint64_t w1 = f32x2_bcast(__int_as_float(e1.y));
        uint4 v0 = *(const uint4*)(x + (size_t)e0.x * C + c8);
        uint4 v1 = *(const uint4*)(x + (size_t)e1.x * C + c8);
        fma_f32x2(A0, h2_to_f32x2(v0.x), w0);
        fma_f32x2(A1, h2_to_f32x2(v0.y), w0);
        fma_f32x2(A2, h2_to_f32x2(v0.z), w0);
        fma_f32x2(A3, h2_to_f32x2(v0.w), w0);
        fma_f32x2(A0, h2_to_f32x2(v1.x), w1);
        fma_f32x2(A1, h2_to_f32x2(v1.y), w1);
        fma_f32x2(A2, h2_to_f32x2(v1.z), w1);
        fma_f32x2(A3, h2_to_f32x2(v1.w), w1);
    }
    if (e < end) {
        int2 e0 = (e < lim) ? scsr[e - bbeg] : g_csr[e];
        uint64_t w0 = f32x2_bcast(__int_as_float(e0.y));
        uint4 v0 = *(const uint4*)(x + (size_t)e0.x * C + c8);
        fma_f32x2(A0, h2_to_f32x2(v0.x), w0);
        fma_f32x2(A1, h2_to_f32x2(v0.y), w0);
        fma_f32x2(A2, h2_to_f32x2(v0.z), w0);
        fma_f32x2(A3, h2_to_f32x2(v0.w), w0);
    }

    float2 a01 = f32x2_unpack(A0), a23 = f32x2_unpack(A1);
    float2 a45 = f32x2_unpack(A2), a67 = f32x2_unpack(A3);

    float m = funkey(g_maxkey);
    float s = (mode ? 2.0f : 1.0f) / m;
    float d = g_deg[node];
    uint4 xv = *(const uint4*)(x + (size_t)node * C + c8);
    float2 x0 = __half22float2(*(__half2*)&xv.x);
    float2 x1 = __half22float2(*(__half2*)&xv.y);
    float2 x2 = __half22float2(*(__half2*)&xv.z);
    float2 x3 = __half22float2(*(__half2*)&xv.w);
    float r0 = s * (d * x0.x - a01.x), r1 = s * (d * x0.y - a01.y);
    float r2 = s * (d * x1.x - a23.x), r3 = s * (d * x1.y - a23.y);
    float r4 = s * (d * x2.x - a45.x), r5 = s * (d * x2.y - a45.y);
    float r6 = s * (d * x3.x - a67.x), r7 = s * (d * x3.y - a67.y);
    if (mode) {
        uint4 pv = *(const uint4*)(prev + (size_t)node * C + c8);
        float2 p0 = __half22float2(*(__half2*)&pv.x);
        float2 p1 = __half22float2(*(__half2*)&pv.y);
        float2 p2 = __half22float2(*(__half2*)&pv.z);
        float2 p3 = __half22float2(*(__half2*)&pv.w);
        r0 -= p0.x; r1 -= p0.y; r2 -= p1.x; r3 -= p1.y;
        r4 -= p2.x; r5 -= p2.y; r6 -= p3.x; r7 -= p3.y;
    }
    uint4 ov;
    *(__half2*)&ov.x = __floats2half2_rn(r0, r1);
    *(__half2*)&ov.y = __floats2half2_rn(r2, r3);
    *(__half2*)&ov.z = __floats2half2_rn(r4, r5);
    *(__half2*)&ov.w = __floats2half2_rn(r6, r7);
    *(uint4*)(o + (size_t)node * C + c8) = ov;
}

// ------- fused fp16 HMMA GEMM (6 terms, cp.async ping-pong) + state cleanup ------
// (R9 form — 256 threads, 8 warps; 512-thread variant was neutral.)
#define XS_H 136
#define TILE_HALFS (128 * XS_H)
#define STAGE_HALFS (2 * TILE_HALFS)
#define SMEM_GEMM_BYTES (2 * STAGE_HALFS * 2)

__global__ __launch_bounds__(256) void k_gemm16(float* __restrict__ out) {
    extern __shared__ __half smh[];
    uint32_t sb = smem_u32(smh);

    int tid = threadIdx.x;

    // self-cleaning for the next replay: zero deg/cnt/maxkey/g_part.
    {
        int n = blockIdx.x * 128 + tid;
        if (tid < 128 && n < N_NODES) { g_deg[n] = 0.f; g_cnt[n] = 0; }
        if (blockIdx.x == 0) {
            if (tid == 0) g_maxkey = 0u;
            if (tid < NB_SCAN) g_part[tid] = 0;
        }
    }

    int wid = tid >> 5, lane = tid & 31;
    int g = lane >> 2, t = lane & 3;
    int wm = wid & 3, wn = wid >> 2;
    int row0 = blockIdx.x * 128;

    auto stage = [&](int b, int kc) {
        const __half* Xp = g_T16[kc];
        const __half* Wp = g_WT16 + kc * (C * C);
        uint32_t xb = sb + (uint32_t)b * STAGE_HALFS * 2;
        uint32_t wb = xb + TILE_HALFS * 2;
        #pragma unroll
        for (int i = 0; i < 8; i++) {
            int idx = tid + i * 256;
            int r = idx >> 4, u = idx & 15;
            int row = row0 + r;
            int ok = (row < N_NODES) ? 16 : 0;
            const __half* xs = Xp + (size_t)(ok ? row : 0) * C + u * 8;
            CP_ASYNC16(xb + (uint32_t)(r * XS_H + u * 8) * 2, xs, ok);
            CP_ASYNC16(wb + (uint32_t)(r * XS_H + u * 8) * 2, Wp + r * C + u * 8, 16);
        }
    };

    float acc[2][8][4];
    #pragma unroll
    for (int mt = 0; mt < 2; mt++)
        #pragma unroll
        for (int nt = 0; nt < 8; nt++)
            #pragma unroll
            for (int j = 0; j < 4; j++) acc[mt][nt][j] = 0.f;

    stage(0, 0);
    CP_COMMIT();
    CP_WAIT0();
    __syncthreads();

    int buf = 0;
    for (int kc = 0; kc < KCHEB; kc++) {
        if (kc + 1 < KCHEB) { stage(buf ^ 1, kc + 1); CP_COMMIT(); }

        const __half* Xs = smh + buf * STAGE_HALFS;
        const __half* Ws = Xs + TILE_HALFS;

        #pragma unroll
        for (int ks = 0; ks < 8; ks++) {
            int kb = ks * 16;
            uint32_t a[2][4];
            #pragma unroll
            for (int mt = 0; mt < 2; mt++) {
                const __half* xr = Xs + (wm * 32 + mt * 16 + g) * XS_H + kb;
                a[mt][0] = *(const uint32_t*)(xr + 2 * t);
                a[mt][1] = *(const uint32_t*)(xr + 8 * XS_H + 2 * t);
                a[mt][2] = *(const uint32_t*)(xr + 2 * t + 8);
                a[mt][3] = *(const uint32_t*)(xr + 8 * XS_H + 2 * t + 8);
            }
            #pragma unroll
            for (int nt = 0; nt < 8; nt++) {
                const __half* wr = Ws + (wn * 64 + nt * 8 + g) * XS_H + kb;
                uint32_t b0 = *(const uint32_t*)(wr + 2 * t);
                uint32_t b1 = *(const uint32_t*)(wr + 2 * t + 8);
                mma_f16(acc[0][nt], a[0][0], a[0][1], a[0][2], a[0][3], b0, b1);
                mma_f16(acc[1][nt], a[1][0], a[1][1], a[1][2], a[1][3], b0, b1);
            }
        }

        if (kc + 1 < KCHEB) CP_WAIT0();
        __syncthreads();
        buf ^= 1;
    }

    #pragma unroll
    for (int mt = 0; mt < 2; mt++) {
        int row_lo = row0 + wm * 32 + mt * 16 + g;
        int row_hi = row_lo + 8;
        #pragma unroll
        for (int nt = 0; nt < 8; nt++) {
            int col = wn * 64 + nt * 8 + 2 * t;
            float b0 = g_bsum[col], b1 = g_bsum[col + 1];
            if (row_lo < N_NODES) {
                float2 v = make_float2(acc[mt][nt][0] + b0, acc[mt][nt][1] + b1);
                *(float2*)(out + (size_t)row_lo * C + col) = v;
            }
            if (row_hi < N_NODES) {
                float2 v = make_float2(acc[mt][nt][2] + b0, acc[mt][nt][3] + b1);
                *(float2*)(out + (size_t)row_hi * C + col) = v;
            }
        }
    }
}

// ---------------- launch ----------------
extern "C" void kernel_launch(void* const* d_in, const int* in_sizes, int n_in,
                              void* d_out, int out_size) {
    const float* nodes     = (const float*)d_in[0];
    const float* edges     = (const float*)d_in[1];
    const int*   senders   = (const int*)d_in[2];
    const int*   receivers = (const int*)d_in[3];
    const float* W         = (const float*)d_in[4];
    const float* b_dense   = (const float*)d_in[5];
    const float* bias      = (const float*)d_in[6];
    float* out = (float*)d_out;

    const int NBLK_I = (N_NODES * C / 2 + 255) / 256;
    const int NBLK_SP = (N_NODES + 15) / 16;   // one block per 16 nodes

    cudaFuncSetAttribute(k_gemm16, cudaFuncAttributeMaxDynamicSharedMemorySize,
                         SMEM_GEMM_BYTES);

    k_init_stats<<<NBLK_I, 256>>>(nodes, edges, senders, W, b_dense, bias);
    k_scan<<<NB_SCAN, 1024>>>();
    k_fill<<<NBLK_E, 256>>>(senders, receivers, edges);

    k_spmv16<<<NBLK_SP, 256>>>(0, 0, 1, 0);
    k_spmv16<<<NBLK_SP, 256>>>(1, 0, 2, 1);
    k_spmv16<<<NBLK_SP, 256>>>(2, 1, 3, 1);
    k_spmv16<<<NBLK_SP, 256>>>(3, 2, 4, 1);
    k_spmv16<<<NBLK_SP, 256>>>(4, 3, 5, 1);

    k_gemm16<<<NTILES, 256, SMEM_GEMM_BYTES>>>(out);
}

// round 14
// speedup vs baseline: 1.0775x; 1.0775x over previous
#include <cuda_runtime.h>
#include <cuda_fp16.h>
#include <cstdint>

#define N_NODES 50000
#define N_EDGES 800000
#define C 128
#define KCHEB 6
#define NB_SCAN ((N_NODES + 1023) / 1024)
#define NTILES ((N_NODES + 127) / 128)
#define NBLK_E ((N_EDGES + 255) / 256)

// ---------------- scratch (device globals: no allocation allowed) ----------------
// g_deg, g_cnt, g_maxkey, g_part are zero at load; the GEMM kernel re-zeros them
// at the end of every launch sequence (self-cleaning), so each replay sees zeros.
__device__ float    g_deg[N_NODES];
__device__ int      g_cnt[N_NODES];
__device__ int      g_rowptr[N_NODES + 1];
__device__ int      g_next[N_NODES];
__device__ int      g_part[NB_SCAN];             // block totals +1 sentinel
__device__ int2     g_csr[N_EDGES];              // {recv, weight bits}
__device__ __half   g_T16[KCHEB][N_NODES * C];   // T0..T5 in fp16
__device__ __half   g_WT16[KCHEB * C * C];       // WT16[k][n][cin] = W[k][cin][n]
__device__ unsigned g_maxkey;
__device__ float    g_bsum[C];                   // sum_k b_dense[k] + bias

// ---------------- helpers ----------------
__device__ __forceinline__ unsigned fkey(float f) {
    unsigned u = __float_as_uint(f);
    return (u & 0x80000000u) ? ~u : (u | 0x80000000u);
}
__device__ __forceinline__ float funkey(unsigned k) {
    return (k & 0x80000000u) ? __uint_as_float(k & 0x7fffffffu) : __uint_as_float(~k);
}

__device__ __forceinline__ void blockMaxKey(unsigned k) {
    int lane = threadIdx.x & 31, wid = threadIdx.x >> 5;
    #pragma unroll
    for (int o = 16; o > 0; o >>= 1) {
        unsigned x = __shfl_down_sync(0xffffffffu, k, o);
        k = k > x ? k : x;
    }
    __shared__ unsigned sm[32];
    if (lane == 0) sm[wid] = k;
    __syncthreads();
    if (wid == 0) {
        int nw = (blockDim.x + 31) >> 5;
        k = (lane < nw) ? sm[lane] : 0u;
        #pragma unroll
        for (int o = 16; o > 0; o >>= 1) {
            unsigned x = __shfl_down_sync(0xffffffffu, k, o);
            k = k > x ? k : x;
        }
        if (lane == 0) atomicMax(&g_maxkey, k);
    }
}

__device__ __forceinline__ void mma_f16(float* c, uint32_t a0, uint32_t a1,
                                        uint32_t a2, uint32_t a3,
                                        uint32_t b0, uint32_t b1) {
    asm volatile(
        "mma.sync.aligned.m16n8k16.row.col.f32.f16.f16.f32 "
        "{%0,%1,%2,%3}, {%4,%5,%6,%7}, {%8,%9}, {%0,%1,%2,%3};"
        : "+f"(c[0]), "+f"(c[1]), "+f"(c[2]), "+f"(c[3])
        : "r"(a0), "r"(a1), "r"(a2), "r"(a3), "r"(b0), "r"(b1));
}

__device__ __forceinline__ uint32_t smem_u32(const void* p) {
    uint32_t a;
    asm("{ .reg .u64 t; cvta.to.shared.u64 t, %1; cvt.u32.u64 %0, t; }" : "=r"(a) : "l"(p));
    return a;
}

// ---- packed f32x2 helpers (Blackwell FFMA2 path, PTX-only) ----
__device__ __forceinline__ uint64_t f32x2_bcast(float w) {
    uint64_t r;
    asm("mov.b64 %0, {%1, %1};" : "=l"(r) : "f"(w));
    return r;
}
__device__ __forceinline__ uint64_t h2_to_f32x2(uint32_t h2) {
    float2 f = __half22float2(*(__half2*)&h2);
    uint64_t r;
    asm("mov.b64 %0, {%1, %2};" : "=l"(r) : "f"(f.x), "f"(f.y));
    return r;
}
__device__ __forceinline__ void fma_f32x2(uint64_t& acc, uint64_t x, uint64_t w2) {
    asm("fma.rn.f32x2 %0, %1, %2, %0;" : "+l"(acc) : "l"(x), "l"(w2));
}
__device__ __forceinline__ float2 f32x2_unpack(uint64_t v) {
    float2 f;
    asm("mov.b64 {%0, %1}, %2;" : "=f"(f.x), "=f"(f.y) : "l"(v));
    return f;
}

#define CP_ASYNC16(dst, src, sz) \
    asm volatile("cp.async.cg.shared.global [%0], [%1], 16, %2;" \
        :: "r"(dst), "l"(src), "r"(sz) : "memory")
#define CP_COMMIT() asm volatile("cp.async.commit_group;" ::: "memory")
#define CP_WAIT0()  asm volatile("cp.async.wait_group 0;" ::: "memory")

// -------- merged setup + edge stats (deg/cnt/maxkey pre-zeroed by cleanup) -------
__global__ void k_init_stats(const float* __restrict__ nodes, const float* __restrict__ edges,
                             const int* __restrict__ senders, const float* __restrict__ W,
                             const float* __restrict__ bd, const float* __restrict__ bias) {
    unsigned i = blockIdx.x * blockDim.x + threadIdx.x;
    if (i < (unsigned)(N_NODES * C / 2)) {
        float2 f = *(const float2*)(nodes + (size_t)i * 2);
        *(__half2*)&g_T16[0][(size_t)i * 2] = __floats2half2_rn(f.x, f.y);
    }
    if (i < (unsigned)(KCHEB * C * C)) {
        unsigned kc = i >> 14, rem = i & 16383;
        unsigned n = rem >> 7, k = rem & 127;
        g_WT16[i] = __float2half(W[kc * C * C + k * C + n]);
    }
    if (i < C) {
        float s = bias[i];
        #pragma unroll
        for (int k = 0; k < KCHEB; k++) s += bd[k * C + i];
        g_bsum[i] = s;
    }
    if (blockIdx.x < NBLK_E) {
        unsigned key = 0u;
        if (i < N_EDGES) {
            float w = edges[i];
            int s = senders[i];
            atomicAdd(&g_deg[s], w);
            atomicAdd(&g_cnt[s], 1);
            key = fkey(-w);
        }
        blockMaxKey(key);
    }
}

// -------- single-pass scan (49 co-resident blocks, sentinel lookback) + deg max --
__global__ __launch_bounds__(1024) void k_scan() {
    int t = threadIdx.x;
    int b = blockIdx.x;
    int i = b * 1024 + t;
    int v = (i < N_NODES) ? g_cnt[i] : 0;
    unsigned dkey = (i < N_NODES) ? fkey(g_deg[i]) : 0u;
    int lane = t & 31, wid = t >> 5;
    int incl = v;
    #pragma unroll
    for (int o = 1; o < 32; o <<= 1) {
        int n = __shfl_up_sync(0xffffffffu, incl, o);
        if (lane >= o) incl += n;
    }
    __shared__ int ws[32];
    if (lane == 31) ws[wid] = incl;
    __syncthreads();
    if (wid == 0) {
        int x = ws[lane];
        int ix = x;
        #pragma unroll
        for (int o = 1; o < 32; o <<= 1) {
            int n = __shfl_up_sync(0xffffffffu, ix, o);
            if (lane >= o) ix += n;
        }
        ws[lane] = ix - x;
    }
    __syncthreads();
    int excl = incl - v + ws[wid];

    // publish this block's total (+1 sentinel; g_part pre-zeroed by cleanup)
    if (t == 1023) atomicExch(&g_part[b], excl + v + 1);

    // parallel wait for all predecessor totals
    __shared__ int psum[64];
    __shared__ int pre_sh;
    if (t < b) {
        int val;
        do { val = *(volatile int*)&g_part[t]; } while (val == 0);
        psum[t] = val - 1;
    }
    __syncthreads();
    if (t == 0) {
        int s = 0;
        for (int p = 0; p < b; p++) s += psum[p];
        pre_sh = s;
    }
    __syncthreads();

    int rp = excl + pre_sh;
    if (i < N_NODES) { g_rowptr[i] = rp; g_next[i] = rp; }
    if (b == NB_SCAN - 1 && t == 1023) g_rowptr[N_NODES] = rp + v;

    blockMaxKey(dkey);
}

__global__ void k_fill(const int* __restrict__ senders, const int* __restrict__ receivers,
                       const float* __restrict__ edges) {
    int e = blockIdx.x * blockDim.x + threadIdx.x;
    if (e < N_EDGES) {
        int s = senders[e];
        int p = atomicAdd(&g_next[s], 1);
        g_csr[p] = make_int2(receivers[e], __float_as_int(edges[e]));
    }
}

// ---------------- fused fp16 Laplacian matvec + Chebyshev combine ----------------
// half-warp per node; lane covers 8 halfs (uint4); 2-edge unroll; f32x2 packed FMA.
// (R9 form — proven operating point: regs=32, occ~78%, ~82% of L2 roofline. FROZEN.)
__global__ __launch_bounds__(256) void k_spmv16(int in_s, int prev_s, int out_s, int mode) {
    const __half* x = g_T16[in_s];
    const __half* prev = g_T16[prev_s];
    __half* o = g_T16[out_s];

    int node = (blockIdx.x * blockDim.x + threadIdx.x) >> 4;
    int l = threadIdx.x & 15;
    if (node >= N_NODES) return;

    int beg = g_rowptr[node], end = g_rowptr[node + 1];
    int c8 = l * 8;
    uint64_t A0 = 0ull, A1 = 0ull, A2 = 0ull, A3 = 0ull;  // packed {f32,f32} accumulators

    int e = beg;
    for (; e + 2 <= end; e += 2) {
        int2 e0 = g_csr[e], e1 = g_csr[e + 1];
        uint64_t w0 = f32x2_bcast(__int_as_float(e0.y));
        uint64_t w1 = f32x2_bcast(__int_as_float(e1.y));
        uint4 v0 = *(const uint4*)(x + (size_t)e0.x * C + c8);
        uint4 v1 = *(const uint4*)(x + (size_t)e1.x * C + c8);
        fma_f32x2(A0, h2_to_f32x2(v0.x), w0);
        fma_f32x2(A1, h2_to_f32x2(v0.y), w0);
        fma_f32x2(A2, h2_to_f32x2(v0.z), w0);
        fma_f32x2(A3, h2_to_f32x2(v0.w), w0);
        fma_f32x2(A0, h2_to_f32x2(v1.x), w1);
        fma_f32x2(A1, h2_to_f32x2(v1.y), w1);
        fma_f32x2(A2, h2_to_f32x2(v1.z), w1);
        fma_f32x2(A3, h2_to_f32x2(v1.w), w1);
    }
    if (e < end) {
        int2 e0 = g_csr[e];
        uint64_t w0 = f32x2_bcast(__int_as_float(e0.y));
        uint4 v0 = *(const uint4*)(x + (size_t)e0.x * C + c8);
        fma_f32x2(A0, h2_to_f32x2(v0.x), w0);
        fma_f32x2(A1, h2_to_f32x2(v0.y), w0);
        fma_f32x2(A2, h2_to_f32x2(v0.z), w0);
        fma_f32x2(A3, h2_to_f32x2(v0.w), w0);
    }

    float2 a01 = f32x2_unpack(A0), a23 = f32x2_unpack(A1);
    float2 a45 = f32x2_unpack(A2), a67 = f32x2_unpack(A3);

    float m = funkey(g_maxkey);
    float s = (mode ? 2.0f : 1.0f) / m;
    float d = g_deg[node];
    uint4 xv = *(const uint4*)(x + (size_t)node * C + c8);
    float2 x0 = __half22float2(*(__half2*)&xv.x);
    float2 x1 = __half22float2(*(__half2*)&xv.y);
    float2 x2 = __half22float2(*(__half2*)&xv.z);
    float2 x3 = __half22float2(*(__half2*)&xv.w);
    float r0 = s * (d * x0.x - a01.x), r1 = s * (d * x0.y - a01.y);
    float r2 = s * (d * x1.x - a23.x), r3 = s * (d * x1.y - a23.y);
    float r4 = s * (d * x2.x - a45.x), r5 = s * (d * x2.y - a45.y);
    float r6 = s * (d * x3.x - a67.x), r7 = s * (d * x3.y - a67.y);
    if (mode) {
        uint4 pv = *(const uint4*)(prev + (size_t)node * C + c8);
        float2 p0 = __half22float2(*(__half2*)&pv.x);
        float2 p1 = __half22float2(*(__half2*)&pv.y);
        float2 p2 = __half22float2(*(__half2*)&pv.z);
        float2 p3 = __half22float2(*(__half2*)&pv.w);
        r0 -= p0.x; r1 -= p0.y; r2 -= p1.x; r3 -= p1.y;
        r4 -= p2.x; r5 -= p2.y; r6 -= p3.x; r7 -= p3.y;
    }
    uint4 ov;
    *(__half2*)&ov.x = __floats2half2_rn(r0, r1);
    *(__half2*)&ov.y = __floats2half2_rn(r2, r3);
    *(__half2*)&ov.z = __floats2half2_rn(r4, r5);
    *(__half2*)&ov.w = __floats2half2_rn(r6, r7);
    *(uint4*)(o + (size_t)node * C + c8) = ov;
}

// ------- fused fp16 HMMA GEMM (6 terms) + state cleanup -------------------------
// Single-buffered stage (69.6KB smem) at 2 CTAs/SM: two independent CTAs per SM
// interleave stage/compute phases (decoupled barriers), waves 2.64 -> 1.32.
#define XS_H 136
#define TILE_HALFS (128 * XS_H)
#define STAGE_HALFS (2 * TILE_HALFS)
#define SMEM_GEMM_BYTES (STAGE_HALFS * 2)

__global__ __launch_bounds__(256, 2) void k_gemm16(float* __restrict__ out) {
    extern __shared__ __half smh[];
    uint32_t sb = smem_u32(smh);

    int tid = threadIdx.x;

    // self-cleaning for the next replay: zero deg/cnt/maxkey/g_part.
    {
        int n = blockIdx.x * 128 + tid;
        if (tid < 128 && n < N_NODES) { g_deg[n] = 0.f; g_cnt[n] = 0; }
        if (blockIdx.x == 0) {
            if (tid == 0) g_maxkey = 0u;
            if (tid < NB_SCAN) g_part[tid] = 0;
        }
    }

    int wid = tid >> 5, lane = tid & 31;
    int g = lane >> 2, t = lane & 3;
    int wm = wid & 3, wn = wid >> 2;
    int row0 = blockIdx.x * 128;

    const __half* Xs = smh;
    const __half* Ws = smh + TILE_HALFS;

    auto stage = [&](int kc) {
        const __half* Xp = g_T16[kc];
        const __half* Wp = g_WT16 + kc * (C * C);
        uint32_t xb = sb;
        uint32_t wb = sb + TILE_HALFS * 2;
        #pragma unroll
        for (int i = 0; i < 8; i++) {
            int idx = tid + i * 256;
            int r = idx >> 4, u = idx & 15;
            int row = row0 + r;
            int ok = (row < N_NODES) ? 16 : 0;
            const __half* xs = Xp + (size_t)(ok ? row : 0) * C + u * 8;
            CP_ASYNC16(xb + (uint32_t)(r * XS_H + u * 8) * 2, xs, ok);
            CP_ASYNC16(wb + (uint32_t)(r * XS_H + u * 8) * 2, Wp + r * C + u * 8, 16);
        }
        CP_COMMIT();
    };

    float acc[2][8][4];
    #pragma unroll
    for (int mt = 0; mt < 2; mt++)
        #pragma unroll
        for (int nt = 0; nt < 8; nt++)
            #pragma unroll
            for (int j = 0; j < 4; j++) acc[mt][nt][j] = 0.f;

    for (int kc = 0; kc < KCHEB; kc++) {
        stage(kc);
        CP_WAIT0();
        __syncthreads();

        #pragma unroll
        for (int ks = 0; ks < 8; ks++) {
            int kb = ks * 16;
            uint32_t a[2][4];
            #pragma unroll
            for (int mt = 0; mt < 2; mt++) {
                const __half* xr = Xs + (wm * 32 + mt * 16 + g) * XS_H + kb;
                a[mt][0] = *(const uint32_t*)(xr + 2 * t);
                a[mt][1] = *(const uint32_t*)(xr + 8 * XS_H + 2 * t);
                a[mt][2] = *(const uint32_t*)(xr + 2 * t + 8);
                a[mt][3] = *(const uint32_t*)(xr + 8 * XS_H + 2 * t + 8);
            }
            #pragma unroll
            for (int nt = 0; nt < 8; nt++) {
                const __half* wr = Ws + (wn * 64 + nt * 8 + g) * XS_H + kb;
                uint32_t b0 = *(const uint32_t*)(wr + 2 * t);
                uint32_t b1 = *(const uint32_t*)(wr + 2 * t + 8);
                mma_f16(acc[0][nt], a[0][0], a[0][1], a[0][2], a[0][3], b0, b1);
                mma_f16(acc[1][nt], a[1][0], a[1][1], a[1][2], a[1][3], b0, b1);
            }
        }
        __syncthreads();
    }

    #pragma unroll
    for (int mt = 0; mt < 2; mt++) {
        int row_lo = row0 + wm * 32 + mt * 16 + g;
        int row_hi = row_lo + 8;
        #pragma unroll
        for (int nt = 0; nt < 8; nt++) {
            int col = wn * 64 + nt * 8 + 2 * t;
            float b0 = g_bsum[col], b1 = g_bsum[col + 1];
            if (row_lo < N_NODES) {
                float2 v = make_float2(acc[mt][nt][0] + b0, acc[mt][nt][1] + b1);
                *(float2*)(out + (size_t)row_lo * C + col) = v;
            }
            if (row_hi < N_NODES) {
                float2 v = make_float2(acc[mt][nt][2] + b0, acc[mt][nt][3] + b1);
                *(float2*)(out + (size_t)row_hi * C + col) = v;
            }
        }
    }
}

// ---------------- launch ----------------
extern "C" void kernel_launch(void* const* d_in, const int* in_sizes, int n_in,
                              void* d_out, int out_size) {
    const float* nodes     = (const float*)d_in[0];
    const float* edges     = (const float*)d_in[1];
    const int*   senders   = (const int*)d_in[2];
    const int*   receivers = (const int*)d_in[3];
    const float* W         = (const float*)d_in[4];
    const float* b_dense   = (const float*)d_in[5];
    const float* bias      = (const float*)d_in[6];
    float* out = (float*)d_out;

    const int NBLK_I = (N_NODES * C / 2 + 255) / 256;
    const int NBLK_S = (N_NODES * 16 + 255) / 256;

    cudaFuncSetAttribute(k_gemm16, cudaFuncAttributeMaxDynamicSharedMemorySize,
                         SMEM_GEMM_BYTES);

    k_init_stats<<<NBLK_I, 256>>>(nodes, edges, senders, W, b_dense, bias);
    k_scan<<<NB_SCAN, 1024>>>();
    k_fill<<<NBLK_E, 256>>>(senders, receivers, edges);

    k_spmv16<<<NBLK_S, 256>>>(0, 0, 1, 0);
    k_spmv16<<<NBLK_S, 256>>>(1, 0, 2, 1);
    k_spmv16<<<NBLK_S, 256>>>(2, 1, 3, 1);
    k_spmv16<<<NBLK_S, 256>>>(3, 2, 4, 1);
    k_spmv16<<<NBLK_S, 256>>>(4, 3, 5, 1);

    k_gemm16<<<NTILES, 256, SMEM_GEMM_BYTES>>>(out);
}

// round 15
// speedup vs baseline: 1.0784x; 1.0008x over previous
#include <cuda_runtime.h>
#include <cuda_fp16.h>
#include <cstdint>

#define N_NODES 50000
#define N_EDGES 800000
#define C 128
#define KCHEB 6
#define NB_SCAN ((N_NODES + 1023) / 1024)
#define NTILES ((N_NODES + 127) / 128)
#define NBLK_E ((N_EDGES + 255) / 256)

// ---------------- scratch (device globals: no allocation allowed) ----------------
// g_deg, g_cnt, g_maxkey, g_part are zero at load; the GEMM kernel re-zeros them
// at the end of every launch sequence (self-cleaning), so each replay sees zeros.
__device__ float    g_deg[N_NODES];
__device__ int      g_cnt[N_NODES];
__device__ int      g_rowptr[N_NODES + 1];
__device__ int      g_next[N_NODES];
__device__ int      g_part[NB_SCAN];             // block totals +1 sentinel
__device__ __align__(16) int2 g_csr[N_EDGES];    // {recv * C (pre-mul), weight bits}
__device__ __half   g_T16[KCHEB][N_NODES * C];   // T0..T5 in fp16
__device__ __half   g_WT16[KCHEB * C * C];       // WT16[k][n][cin] = W[k][cin][n]
__device__ unsigned g_maxkey;
__device__ float    g_bsum[C];                   // sum_k b_dense[k] + bias

// ---------------- helpers ----------------
__device__ __forceinline__ unsigned fkey(float f) {
    unsigned u = __float_as_uint(f);
    return (u & 0x80000000u) ? ~u : (u | 0x80000000u);
}
__device__ __forceinline__ float funkey(unsigned k) {
    return (k & 0x80000000u) ? __uint_as_float(k & 0x7fffffffu) : __uint_as_float(~k);
}

__device__ __forceinline__ void blockMaxKey(unsigned k) {
    int lane = threadIdx.x & 31, wid = threadIdx.x >> 5;
    #pragma unroll
    for (int o = 16; o > 0; o >>= 1) {
        unsigned x = __shfl_down_sync(0xffffffffu, k, o);
        k = k > x ? k : x;
    }
    __shared__ unsigned sm[32];
    if (lane == 0) sm[wid] = k;
    __syncthreads();
    if (wid == 0) {
        int nw = (blockDim.x + 31) >> 5;
        k = (lane < nw) ? sm[lane] : 0u;
        #pragma unroll
        for (int o = 16; o > 0; o >>= 1) {
            unsigned x = __shfl_down_sync(0xffffffffu, k, o);
            k = k > x ? k : x;
        }
        if (lane == 0) atomicMax(&g_maxkey, k);
    }
}

__device__ __forceinline__ void mma_f16(float* c, uint32_t a0, uint32_t a1,
                                        uint32_t a2, uint32_t a3,
                                        uint32_t b0, uint32_t b1) {
    asm volatile(
        "mma.sync.aligned.m16n8k16.row.col.f32.f16.f16.f32 "
        "{%0,%1,%2,%3}, {%4,%5,%6,%7}, {%8,%9}, {%0,%1,%2,%3};"
        : "+f"(c[0]), "+f"(c[1]), "+f"(c[2]), "+f"(c[3])
        : "r"(a0), "r"(a1), "r"(a2), "r"(a3), "r"(b0), "r"(b1));
}

__device__ __forceinline__ uint32_t smem_u32(const void* p) {
    uint32_t a;
    asm("{ .reg .u64 t; cvta.to.shared.u64 t, %1; cvt.u32.u64 %0, t; }" : "=r"(a) : "l"(p));
    return a;
}

// ---- packed f32x2 helpers (Blackwell FFMA2 path, PTX-only) ----
__device__ __forceinline__ uint64_t f32x2_bcast(float w) {
    uint64_t r;
    asm("mov.b64 %0, {%1, %1};" : "=l"(r) : "f"(w));
    return r;
}
__device__ __forceinline__ uint64_t h2_to_f32x2(uint32_t h2) {
    float2 f = __half22float2(*(__half2*)&h2);
    uint64_t r;
    asm("mov.b64 %0, {%1, %2};" : "=l"(r) : "f"(f.x), "f"(f.y));
    return r;
}
__device__ __forceinline__ void fma_f32x2(uint64_t& acc, uint64_t x, uint64_t w2) {
    asm("fma.rn.f32x2 %0, %1, %2, %0;" : "+l"(acc) : "l"(x), "l"(w2));
}
__device__ __forceinline__ float2 f32x2_unpack(uint64_t v) {
    float2 f;
    asm("mov.b64 {%0, %1}, %2;" : "=f"(f.x), "=f"(f.y) : "l"(v));
    return f;
}

#define CP_ASYNC16(dst, src, sz) \
    asm volatile("cp.async.cg.shared.global [%0], [%1], 16, %2;" \
        :: "r"(dst), "l"(src), "r"(sz) : "memory")
#define CP_COMMIT() asm volatile("cp.async.commit_group;" ::: "memory")
#define CP_WAIT0()  asm volatile("cp.async.wait_group 0;" ::: "memory")

// -------- merged setup + edge stats (deg/cnt/maxkey pre-zeroed by cleanup) -------
__global__ void k_init_stats(const float* __restrict__ nodes, const float* __restrict__ edges,
                             const int* __restrict__ senders, const float* __restrict__ W,
                             const float* __restrict__ bd, const float* __restrict__ bias) {
    unsigned i = blockIdx.x * blockDim.x + threadIdx.x;
    if (i < (unsigned)(N_NODES * C / 2)) {
        float2 f = *(const float2*)(nodes + (size_t)i * 2);
        *(__half2*)&g_T16[0][(size_t)i * 2] = __floats2half2_rn(f.x, f.y);
    }
    if (i < (unsigned)(KCHEB * C * C)) {
        unsigned kc = i >> 14, rem = i & 16383;
        unsigned n = rem >> 7, k = rem & 127;
        g_WT16[i] = __float2half(W[kc * C * C + k * C + n]);
    }
    if (i < C) {
        float s = bias[i];
        #pragma unroll
        for (int k = 0; k < KCHEB; k++) s += bd[k * C + i];
        g_bsum[i] = s;
    }
    if (blockIdx.x < NBLK_E) {
        unsigned key = 0u;
        if (i < N_EDGES) {
            float w = edges[i];
            int s = senders[i];
            atomicAdd(&g_deg[s], w);
            atomicAdd(&g_cnt[s], 1);
            key = fkey(-w);
        }
        blockMaxKey(key);
    }
}

// -------- single-pass scan (49 co-resident blocks, sentinel lookback) + deg max --
__global__ __launch_bounds__(1024) void k_scan() {
    int t = threadIdx.x;
    int b = blockIdx.x;
    int i = b * 1024 + t;
    int v = (i < N_NODES) ? g_cnt[i] : 0;
    unsigned dkey = (i < N_NODES) ? fkey(g_deg[i]) : 0u;
    int lane = t & 31, wid = t >> 5;
    int incl = v;
    #pragma unroll
    for (int o = 1; o < 32; o <<= 1) {
        int n = __shfl_up_sync(0xffffffffu, incl, o);
        if (lane >= o) incl += n;
    }
    __shared__ int ws[32];
    if (lane == 31) ws[wid] = incl;
    __syncthreads();
    if (wid == 0) {
        int x = ws[lane];
        int ix = x;
        #pragma unroll
        for (int o = 1; o < 32; o <<= 1) {
            int n = __shfl_up_sync(0xffffffffu, ix, o);
            if (lane >= o) ix += n;
        }
        ws[lane] = ix - x;
    }
    __syncthreads();
    int excl = incl - v + ws[wid];

    // publish this block's total (+1 sentinel; g_part pre-zeroed by cleanup)
    if (t == 1023) atomicExch(&g_part[b], excl + v + 1);

    // parallel wait for all predecessor totals
    __shared__ int psum[64];
    __shared__ int pre_sh;
    if (t < b) {
        int val;
        do { val = *(volatile int*)&g_part[t]; } while (val == 0);
        psum[t] = val - 1;
    }
    __syncthreads();
    if (t == 0) {
        int s = 0;
        for (int p = 0; p < b; p++) s += psum[p];
        pre_sh = s;
    }
    __syncthreads();

    int rp = excl + pre_sh;
    if (i < N_NODES) { g_rowptr[i] = rp; g_next[i] = rp; }
    if (b == NB_SCAN - 1 && t == 1023) g_rowptr[N_NODES] = rp + v;

    blockMaxKey(dkey);
}

__global__ void k_fill(const int* __restrict__ senders, const int* __restrict__ receivers,
                       const float* __restrict__ edges) {
    int e = blockIdx.x * blockDim.x + threadIdx.x;
    if (e < N_EDGES) {
        int s = senders[e];
        int p = atomicAdd(&g_next[s], 1);
        // pre-multiplied gather offset: recv * C (half elements)
        g_csr[p] = make_int2(receivers[e] * C, __float_as_int(edges[e]));
    }
}

// ---------------- fused fp16 Laplacian matvec + Chebyshev combine ----------------
// half-warp per node; lane covers 8 halfs (uint4); f32x2 packed FMA; pre-mul CSR
// offsets + paired LDG.128 CSR loads (even-index int4). Numeric order unchanged.
__global__ __launch_bounds__(256) void k_spmv16(int in_s, int prev_s, int out_s, int mode) {
    const __half* x = g_T16[in_s];
    const __half* prev = g_T16[prev_s];
    __half* o = g_T16[out_s];

    int node = (blockIdx.x * blockDim.x + threadIdx.x) >> 4;
    int l = threadIdx.x & 15;
    if (node >= N_NODES) return;

    int beg = g_rowptr[node], end = g_rowptr[node + 1];
    int c8 = l * 8;
    uint64_t A0 = 0ull, A1 = 0ull, A2 = 0ull, A3 = 0ull;  // packed {f32,f32} accumulators

    int e = beg;
    // head: align e to even index for 16B-paired CSR loads
    if (e < end && (e & 1)) {
        int2 e0 = g_csr[e];
        uint64_t w0 = f32x2_bcast(__int_as_float(e0.y));
        uint4 v0 = *(const uint4*)(x + e0.x + c8);
        fma_f32x2(A0, h2_to_f32x2(v0.x), w0);
        fma_f32x2(A1, h2_to_f32x2(v0.y), w0);
        fma_f32x2(A2, h2_to_f32x2(v0.z), w0);
        fma_f32x2(A3, h2_to_f32x2(v0.w), w0);
        e++;
    }
    for (; e + 2 <= end; e += 2) {
        int4 pr = *(const int4*)&g_csr[e];   // two edges in one LDG.128
        uint64_t w0 = f32x2_bcast(__int_as_float(pr.y));
        uint64_t w1 = f32x2_bcast(__int_as_float(pr.w));
        uint4 v0 = *(const uint4*)(x + pr.x + c8);
        uint4 v1 = *(const uint4*)(x + pr.z + c8);
        fma_f32x2(A0, h2_to_f32x2(v0.x), w0);
        fma_f32x2(A1, h2_to_f32x2(v0.y), w0);
        fma_f32x2(A2, h2_to_f32x2(v0.z), w0);
        fma_f32x2(A3, h2_to_f32x2(v0.w), w0);
        fma_f32x2(A0, h2_to_f32x2(v1.x), w1);
        fma_f32x2(A1, h2_to_f32x2(v1.y), w1);
        fma_f32x2(A2, h2_to_f32x2(v1.z), w1);
        fma_f32x2(A3, h2_to_f32x2(v1.w), w1);
    }
    if (e < end) {
        int2 e0 = g_csr[e];
        uint64_t w0 = f32x2_bcast(__int_as_float(e0.y));
        uint4 v0 = *(const uint4*)(x + e0.x + c8);
        fma_f32x2(A0, h2_to_f32x2(v0.x), w0);
        fma_f32x2(A1, h2_to_f32x2(v0.y), w0);
        fma_f32x2(A2, h2_to_f32x2(v0.z), w0);
        fma_f32x2(A3, h2_to_f32x2(v0.w), w0);
    }

    float2 a01 = f32x2_unpack(A0), a23 = f32x2_unpack(A1);
    float2 a45 = f32x2_unpack(A2), a67 = f32x2_unpack(A3);

    float m = funkey(g_maxkey);
    float s = (mode ? 2.0f : 1.0f) / m;
    float d = g_deg[node];
    uint4 xv = *(const uint4*)(x + (size_t)node * C + c8);
    float2 x0 = __half22float2(*(__half2*)&xv.x);
    float2 x1 = __half22float2(*(__half2*)&xv.y);
    float2 x2 = __half22float2(*(__half2*)&xv.z);
    float2 x3 = __half22float2(*(__half2*)&xv.w);
    float r0 = s * (d * x0.x - a01.x), r1 = s * (d * x0.y - a01.y);
    float r2 = s * (d * x1.x - a23.x), r3 = s * (d * x1.y - a23.y);
    float r4 = s * (d * x2.x - a45.x), r5 = s * (d * x2.y - a45.y);
    float r6 = s * (d * x3.x - a67.x), r7 = s * (d * x3.y - a67.y);
    if (mode) {
        uint4 pv = *(const uint4*)(prev + (size_t)node * C + c8);
        float2 p0 = __half22float2(*(__half2*)&pv.x);
        float2 p1 = __half22float2(*(__half2*)&pv.y);
        float2 p2 = __half22float2(*(__half2*)&pv.z);
        float2 p3 = __half22float2(*(__half2*)&pv.w);
        r0 -= p0.x; r1 -= p0.y; r2 -= p1.x; r3 -= p1.y;
        r4 -= p2.x; r5 -= p2.y; r6 -= p3.x; r7 -= p3.y;
    }
    uint4 ov;
    *(__half2*)&ov.x = __floats2half2_rn(r0, r1);
    *(__half2*)&ov.y = __floats2half2_rn(r2, r3);
    *(__half2*)&ov.z = __floats2half2_rn(r4, r5);
    *(__half2*)&ov.w = __floats2half2_rn(r6, r7);
    *(uint4*)(o + (size_t)node * C + c8) = ov;
}

// ------- fused fp16 HMMA GEMM (6 terms) + state cleanup -------------------------
// Single-buffered stage (69.6KB smem) at 2 CTAs/SM (R14 form — best known).
#define XS_H 136
#define TILE_HALFS (128 * XS_H)
#define STAGE_HALFS (2 * TILE_HALFS)
#define SMEM_GEMM_BYTES (STAGE_HALFS * 2)

__global__ __launch_bounds__(256, 2) void k_gemm16(float* __restrict__ out) {
    extern __shared__ __half smh[];
    uint32_t sb = smem_u32(smh);

    int tid = threadIdx.x;

    // self-cleaning for the next replay: zero deg/cnt/maxkey/g_part.
    {
        int n = blockIdx.x * 128 + tid;
        if (tid < 128 && n < N_NODES) { g_deg[n] = 0.f; g_cnt[n] = 0; }
        if (blockIdx.x == 0) {
            if (tid == 0) g_maxkey = 0u;
            if (tid < NB_SCAN) g_part[tid] = 0;
        }
    }

    int wid = tid >> 5, lane = tid & 31;
    int g = lane >> 2, t = lane & 3;
    int wm = wid & 3, wn = wid >> 2;
    int row0 = blockIdx.x * 128;

    const __half* Xs = smh;
    const __half* Ws = smh + TILE_HALFS;

    auto stage = [&](int kc) {
        const __half* Xp = g_T16[kc];
        const __half* Wp = g_WT16 + kc * (C * C);
        uint32_t xb = sb;
        uint32_t wb = sb + TILE_HALFS * 2;
        #pragma unroll
        for (int i = 0; i < 8; i++) {
            int idx = tid + i * 256;
            int r = idx >> 4, u = idx & 15;
            int row = row0 + r;
            int ok = (row < N_NODES) ? 16 : 0;
            const __half* xs = Xp + (size_t)(ok ? row : 0) * C + u * 8;
            CP_ASYNC16(xb + (uint32_t)(r * XS_H + u * 8) * 2, xs, ok);
            CP_ASYNC16(wb + (uint32_t)(r * XS_H + u * 8) * 2, Wp + r * C + u * 8, 16);
        }
        CP_COMMIT();
    };

    float acc[2][8][4];
    #pragma unroll
    for (int mt = 0; mt < 2; mt++)
        #pragma unroll
        for (int nt = 0; nt < 8; nt++)
            #pragma unroll
            for (int j = 0; j < 4; j++) acc[mt][nt][j] = 0.f;

    for (int kc = 0; kc < KCHEB; kc++) {
        stage(kc);
        CP_WAIT0();
        __syncthreads();

        #pragma unroll
        for (int ks = 0; ks < 8; ks++) {
            int kb = ks * 16;
            uint32_t a[2][4];
            #pragma unroll
            for (int mt = 0; mt < 2; mt++) {
                const __half* xr = Xs + (wm * 32 + mt * 16 + g) * XS_H + kb;
                a[mt][0] = *(const uint32_t*)(xr + 2 * t);
                a[mt][1] = *(const uint32_t*)(xr + 8 * XS_H + 2 * t);
                a[mt][2] = *(const uint32_t*)(xr + 2 * t + 8);
                a[mt][3] = *(const uint32_t*)(xr + 8 * XS_H + 2 * t + 8);
            }
            #pragma unroll
            for (int nt = 0; nt < 8; nt++) {
                const __half* wr = Ws + (wn * 64 + nt * 8 + g) * XS_H + kb;
                uint32_t b0 = *(const uint32_t*)(wr + 2 * t);
                uint32_t b1 = *(const uint32_t*)(wr + 2 * t + 8);
                mma_f16(acc[0][nt], a[0][0], a[0][1], a[0][2], a[0][3], b0, b1);
                mma_f16(acc[1][nt], a[1][0], a[1][1], a[1][2], a[1][3], b0, b1);
            }
        }
        __syncthreads();
    }

    #pragma unroll
    for (int mt = 0; mt < 2; mt++) {
        int row_lo = row0 + wm * 32 + mt * 16 + g;
        int row_hi = row_lo + 8;
        #pragma unroll
        for (int nt = 0; nt < 8; nt++) {
            int col = wn * 64 + nt * 8 + 2 * t;
            float b0 = g_bsum[col], b1 = g_bsum[col + 1];
            if (row_lo < N_NODES) {
                float2 v = make_float2(acc[mt][nt][0] + b0, acc[mt][nt][1] + b1);
                *(float2*)(out + (size_t)row_lo * C + col) = v;
            }
            if (row_hi < N_NODES) {
                float2 v = make_float2(acc[mt][nt][2] + b0, acc[mt][nt][3] + b1);
                *(float2*)(out + (size_t)row_hi * C + col) = v;
            }
        }
    }
}

// ---------------- launch ----------------
extern "C" void kernel_launch(void* const* d_in, const int* in_sizes, int n_in,
                              void* d_out, int out_size) {
    const float* nodes     = (const float*)d_in[0];
    const float* edges     = (const float*)d_in[1];
    const int*   senders   = (const int*)d_in[2];
    const int*   receivers = (const int*)d_in[3];
    const float* W         = (const float*)d_in[4];
    const float* b_dense   = (const float*)d_in[5];
    const float* bias      = (const float*)d_in[6];
    float* out = (float*)d_out;

    const int NBLK_I = (N_NODES * C / 2 + 255) / 256;
    const int NBLK_S = (N_NODES * 16 + 255) / 256;

    cudaFuncSetAttribute(k_gemm16, cudaFuncAttributeMaxDynamicSharedMemorySize,
                         SMEM_GEMM_BYTES);

    k_init_stats<<<NBLK_I, 256>>>(nodes, edges, senders, W, b_dense, bias);
    k_scan<<<NB_SCAN, 1024>>>();
    k_fill<<<NBLK_E, 256>>>(senders, receivers, edges);

    k_spmv16<<<NBLK_S, 256>>>(0, 0, 1, 0);
    k_spmv16<<<NBLK_S, 256>>>(1, 0, 2, 1);
    k_spmv16<<<NBLK_S, 256>>>(2, 1, 3, 1);
    k_spmv16<<<NBLK_S, 256>>>(3, 2, 4, 1);
    k_spmv16<<<NBLK_S, 256>>>(4, 3, 5, 1);

    k_gemm16<<<NTILES, 256, SMEM_GEMM_BYTES>>>(out);
}

// round 16
// speedup vs baseline: 1.1026x; 1.0225x over previous
#include <cuda_runtime.h>
#include <cuda_fp16.h>
#include <cstdint>

#define N_NODES 50000
#define N_EDGES 800000
#define C 128
#define KCHEB 6
#define NB_SCAN ((N_NODES + 1023) / 1024)
#define NTILES ((N_NODES + 127) / 128)
#define NBLK_E ((N_EDGES + 255) / 256)

// ---------------- scratch (device globals: no allocation allowed) ----------------
// g_deg, g_cnt, g_maxkey, g_part are zero at load; the GEMM kernel re-zeros them
// at the end of every launch sequence (self-cleaning), so each replay sees zeros.
__device__ float    g_deg[N_NODES];
__device__ int      g_cnt[N_NODES];
__device__ int      g_rowptr[N_NODES + 1];
__device__ int      g_next[N_NODES];
__device__ int      g_part[NB_SCAN];             // block totals +1 sentinel
__device__ __align__(16) int2 g_csr[N_EDGES];    // {recv * C (pre-mul), weight bits}
__device__ __half   g_T16[KCHEB][N_NODES * C];   // T0..T5 in fp16
__device__ __half   g_WT16[KCHEB * C * C];       // WT16[k][n][cin] = W[k][cin][n]
__device__ unsigned g_maxkey;
__device__ float    g_bsum[C];                   // sum_k b_dense[k] + bias

// ---------------- helpers ----------------
__device__ __forceinline__ unsigned fkey(float f) {
    unsigned u = __float_as_uint(f);
    return (u & 0x80000000u) ? ~u : (u | 0x80000000u);
}
__device__ __forceinline__ float funkey(unsigned k) {
    return (k & 0x80000000u) ? __uint_as_float(k & 0x7fffffffu) : __uint_as_float(~k);
}

__device__ __forceinline__ void blockMaxKey(unsigned k) {
    int lane = threadIdx.x & 31, wid = threadIdx.x >> 5;
    #pragma unroll
    for (int o = 16; o > 0; o >>= 1) {
        unsigned x = __shfl_down_sync(0xffffffffu, k, o);
        k = k > x ? k : x;
    }
    __shared__ unsigned sm[32];
    if (lane == 0) sm[wid] = k;
    __syncthreads();
    if (wid == 0) {
        int nw = (blockDim.x + 31) >> 5;
        k = (lane < nw) ? sm[lane] : 0u;
        #pragma unroll
        for (int o = 16; o > 0; o >>= 1) {
            unsigned x = __shfl_down_sync(0xffffffffu, k, o);
            k = k > x ? k : x;
        }
        if (lane == 0) atomicMax(&g_maxkey, k);
    }
}

__device__ __forceinline__ void mma_f16(float* c, uint32_t a0, uint32_t a1,
                                        uint32_t a2, uint32_t a3,
                                        uint32_t b0, uint32_t b1) {
    asm volatile(
        "mma.sync.aligned.m16n8k16.row.col.f32.f16.f16.f32 "
        "{%0,%1,%2,%3}, {%4,%5,%6,%7}, {%8,%9}, {%0,%1,%2,%3};"
        : "+f"(c[0]), "+f"(c[1]), "+f"(c[2]), "+f"(c[3])
        : "r"(a0), "r"(a1), "r"(a2), "r"(a3), "r"(b0), "r"(b1));
}

__device__ __forceinline__ uint32_t smem_u32(const void* p) {
    uint32_t a;
    asm("{ .reg .u64 t; cvta.to.shared.u64 t, %1; cvt.u32.u64 %0, t; }" : "=r"(a) : "l"(p));
    return a;
}

// ---- packed f32x2 helpers (Blackwell FFMA2 path, PTX-only) ----
__device__ __forceinline__ uint64_t f32x2_bcast(float w) {
    uint64_t r;
    asm("mov.b64 %0, {%1, %1};" : "=l"(r) : "f"(w));
    return r;
}
__device__ __forceinline__ uint64_t h2_to_f32x2(uint32_t h2) {
    float2 f = __half22float2(*(__half2*)&h2);
    uint64_t r;
    asm("mov.b64 %0, {%1, %2};" : "=l"(r) : "f"(f.x), "f"(f.y));
    return r;
}
__device__ __forceinline__ void fma_f32x2(uint64_t& acc, uint64_t x, uint64_t w2) {
    asm("fma.rn.f32x2 %0, %1, %2, %0;" : "+l"(acc) : "l"(x), "l"(w2));
}
__device__ __forceinline__ float2 f32x2_unpack(uint64_t v) {
    float2 f;
    asm("mov.b64 {%0, %1}, %2;" : "=f"(f.x), "=f"(f.y) : "l"(v));
    return f;
}

#define CP_ASYNC16(dst, src, sz) \
    asm volatile("cp.async.cg.shared.global [%0], [%1], 16, %2;" \
        :: "r"(dst), "l"(src), "r"(sz) : "memory")
#define CP_COMMIT() asm volatile("cp.async.commit_group;" ::: "memory")
#define CP_WAIT0()  asm volatile("cp.async.wait_group 0;" ::: "memory")

// -------- merged setup + edge stats (deg/cnt/maxkey pre-zeroed by cleanup) -------
__global__ void k_init_stats(const float* __restrict__ nodes, const float* __restrict__ edges,
                             const int* __restrict__ senders, const float* __restrict__ W,
                             const float* __restrict__ bd, const float* __restrict__ bias) {
    unsigned i = blockIdx.x * blockDim.x + threadIdx.x;
    if (i < (unsigned)(N_NODES * C / 2)) {
        float2 f = *(const float2*)(nodes + (size_t)i * 2);
        *(__half2*)&g_T16[0][(size_t)i * 2] = __floats2half2_rn(f.x, f.y);
    }
    if (i < (unsigned)(KCHEB * C * C)) {
        unsigned kc = i >> 14, rem = i & 16383;
        unsigned n = rem >> 7, k = rem & 127;
        g_WT16[i] = __float2half(W[kc * C * C + k * C + n]);
    }
    if (i < C) {
        float s = bias[i];
        #pragma unroll
        for (int k = 0; k < KCHEB; k++) s += bd[k * C + i];
        g_bsum[i] = s;
    }
    if (blockIdx.x < NBLK_E) {
        unsigned key = 0u;
        if (i < N_EDGES) {
            float w = edges[i];
            int s = senders[i];
            atomicAdd(&g_deg[s], w);
            atomicAdd(&g_cnt[s], 1);
            key = fkey(-w);
        }
        blockMaxKey(key);
    }
}

// -------- single-pass scan (49 co-resident blocks, sentinel lookback) + deg max --
__global__ __launch_bounds__(1024) void k_scan() {
    int t = threadIdx.x;
    int b = blockIdx.x;
    int i = b * 1024 + t;
    int v = (i < N_NODES) ? g_cnt[i] : 0;
    unsigned dkey = (i < N_NODES) ? fkey(g_deg[i]) : 0u;
    int lane = t & 31, wid = t >> 5;
    int incl = v;
    #pragma unroll
    for (int o = 1; o < 32; o <<= 1) {
        int n = __shfl_up_sync(0xffffffffu, incl, o);
        if (lane >= o) incl += n;
    }
    __shared__ int ws[32];
    if (lane == 31) ws[wid] = incl;
    __syncthreads();
    if (wid == 0) {
        int x = ws[lane];
        int ix = x;
        #pragma unroll
        for (int o = 1; o < 32; o <<= 1) {
            int n = __shfl_up_sync(0xffffffffu, ix, o);
            if (lane >= o) ix += n;
        }
        ws[lane] = ix - x;
    }
    __syncthreads();
    int excl = incl - v + ws[wid];

    // publish this block's total (+1 sentinel; g_part pre-zeroed by cleanup)
    if (t == 1023) atomicExch(&g_part[b], excl + v + 1);

    // parallel wait for all predecessor totals
    __shared__ int psum[64];
    __shared__ int pre_sh;
    if (t < b) {
        int val;
        do { val = *(volatile int*)&g_part[t]; } while (val == 0);
        psum[t] = val - 1;
    }
    __syncthreads();
    if (t == 0) {
        int s = 0;
        for (int p = 0; p < b; p++) s += psum[p];
        pre_sh = s;
    }
    __syncthreads();

    int rp = excl + pre_sh;
    if (i < N_NODES) { g_rowptr[i] = rp; g_next[i] = rp; }
    if (b == NB_SCAN - 1 && t == 1023) g_rowptr[N_NODES] = rp + v;

    blockMaxKey(dkey);
}

__global__ void k_fill(const int* __restrict__ senders, const int* __restrict__ receivers,
                       const float* __restrict__ edges) {
    int e = blockIdx.x * blockDim.x + threadIdx.x;
    if (e < N_EDGES) {
        int s = senders[e];
        int p = atomicAdd(&g_next[s], 1);
        // pre-multiplied gather offset: recv * C (half elements)
        g_csr[p] = make_int2(receivers[e] * C, __float_as_int(edges[e]));
    }
}

// ---------------- fused fp16 Laplacian matvec + Chebyshev combine ----------------
// half-warp per node; lane covers 8 halfs (uint4); 2-edge unroll (R14 loop form);
// f32x2 packed FMA; pre-multiplied CSR offsets (no IMAD per gather).
__global__ __launch_bounds__(256) void k_spmv16(int in_s, int prev_s, int out_s, int mode) {
    const __half* x = g_T16[in_s];
    const __half* prev = g_T16[prev_s];
    __half* o = g_T16[out_s];

    int node = (blockIdx.x * blockDim.x + threadIdx.x) >> 4;
    int l = threadIdx.x & 15;
    if (node >= N_NODES) return;

    int beg = g_rowptr[node], end = g_rowptr[node + 1];
    int c8 = l * 8;
    uint64_t A0 = 0ull, A1 = 0ull, A2 = 0ull, A3 = 0ull;  // packed {f32,f32} accumulators

    int e = beg;
    for (; e + 2 <= end; e += 2) {
        int2 e0 = g_csr[e], e1 = g_csr[e + 1];
        uint64_t w0 = f32x2_bcast(__int_as_float(e0.y));
        uint64_t w1 = f32x2_bcast(__int_as_float(e1.y));
        uint4 v0 = *(const uint4*)(x + e0.x + c8);
        uint4 v1 = *(const uint4*)(x + e1.x + c8);
        fma_f32x2(A0, h2_to_f32x2(v0.x), w0);
        fma_f32x2(A1, h2_to_f32x2(v0.y), w0);
        fma_f32x2(A2, h2_to_f32x2(v0.z), w0);
        fma_f32x2(A3, h2_to_f32x2(v0.w), w0);
        fma_f32x2(A0, h2_to_f32x2(v1.x), w1);
        fma_f32x2(A1, h2_to_f32x2(v1.y), w1);
        fma_f32x2(A2, h2_to_f32x2(v1.z), w1);
        fma_f32x2(A3, h2_to_f32x2(v1.w), w1);
    }
    if (e < end) {
        int2 e0 = g_csr[e];
        uint64_t w0 = f32x2_bcast(__int_as_float(e0.y));
        uint4 v0 = *(const uint4*)(x + e0.x + c8);
        fma_f32x2(A0, h2_to_f32x2(v0.x), w0);
        fma_f32x2(A1, h2_to_f32x2(v0.y), w0);
        fma_f32x2(A2, h2_to_f32x2(v0.z), w0);
        fma_f32x2(A3, h2_to_f32x2(v0.w), w0);
    }

    float2 a01 = f32x2_unpack(A0), a23 = f32x2_unpack(A1);
    float2 a45 = f32x2_unpack(A2), a67 = f32x2_unpack(A3);

    float m = funkey(g_maxkey);
    float s = (mode ? 2.0f : 1.0f) / m;
    float d = g_deg[node];
    uint4 xv = *(const uint4*)(x + (size_t)node * C + c8);
    float2 x0 = __half22float2(*(__half2*)&xv.x);
    float2 x1 = __half22float2(*(__half2*)&xv.y);
    float2 x2 = __half22float2(*(__half2*)&xv.z);
    float2 x3 = __half22float2(*(__half2*)&xv.w);
    float r0 = s * (d * x0.x - a01.x), r1 = s * (d * x0.y - a01.y);
    float r2 = s * (d * x1.x - a23.x), r3 = s * (d * x1.y - a23.y);
    float r4 = s * (d * x2.x - a45.x), r5 = s * (d * x2.y - a45.y);
    float r6 = s * (d * x3.x - a67.x), r7 = s * (d * x3.y - a67.y);
    if (mode) {
        uint4 pv = *(const uint4*)(prev + (size_t)node * C + c8);
        float2 p0 = __half22float2(*(__half2*)&pv.x);
        float2 p1 = __half22float2(*(__half2*)&pv.y);
        float2 p2 = __half22float2(*(__half2*)&pv.z);
        float2 p3 = __half22float2(*(__half2*)&pv.w);
        r0 -= p0.x; r1 -= p0.y; r2 -= p1.x; r3 -= p1.y;
        r4 -= p2.x; r5 -= p2.y; r6 -= p3.x; r7 -= p3.y;
    }
    uint4 ov;
    *(__half2*)&ov.x = __floats2half2_rn(r0, r1);
    *(__half2*)&ov.y = __floats2half2_rn(r2, r3);
    *(__half2*)&ov.z = __floats2half2_rn(r4, r5);
    *(__half2*)&ov.w = __floats2half2_rn(r6, r7);
    *(uint4*)(o + (size_t)node * C + c8) = ov;
}

// ------- fused fp16 HMMA GEMM (6 terms) + state cleanup -------------------------
// Single-buffered stage (69.6KB smem) at 2 CTAs/SM (R14 form — best known).
#define XS_H 136
#define TILE_HALFS (128 * XS_H)
#define STAGE_HALFS (2 * TILE_HALFS)
#define SMEM_GEMM_BYTES (STAGE_HALFS * 2)

__global__ __launch_bounds__(256, 2) void k_gemm16(float* __restrict__ out) {
    extern __shared__ __half smh[];
    uint32_t sb = smem_u32(smh);

    int tid = threadIdx.x;

    // self-cleaning for the next replay: zero deg/cnt/maxkey/g_part.
    {
        int n = blockIdx.x * 128 + tid;
        if (tid < 128 && n < N_NODES) { g_deg[n] = 0.f; g_cnt[n] = 0; }
        if (blockIdx.x == 0) {
            if (tid == 0) g_maxkey = 0u;
            if (tid < NB_SCAN) g_part[tid] = 0;
        }
    }

    int wid = tid >> 5, lane = tid & 31;
    int g = lane >> 2, t = lane & 3;
    int wm = wid & 3, wn = wid >> 2;
    int row0 = blockIdx.x * 128;

    const __half* Xs = smh;
    const __half* Ws = smh + TILE_HALFS;

    auto stage = [&](int kc) {
        const __half* Xp = g_T16[kc];
        const __half* Wp = g_WT16 + kc * (C * C);
        uint32_t xb = sb;
        uint32_t wb = sb + TILE_HALFS * 2;
        #pragma unroll
        for (int i = 0; i < 8; i++) {
            int idx = tid + i * 256;
            int r = idx >> 4, u = idx & 15;
            int row = row0 + r;
            int ok = (row < N_NODES) ? 16 : 0;
            const __half* xs = Xp + (size_t)(ok ? row : 0) * C + u * 8;
            CP_ASYNC16(xb + (uint32_t)(r * XS_H + u * 8) * 2, xs, ok);
            CP_ASYNC16(wb + (uint32_t)(r * XS_H + u * 8) * 2, Wp + r * C + u * 8, 16);
        }
        CP_COMMIT();
    };

    float acc[2][8][4];
    #pragma unroll
    for (int mt = 0; mt < 2; mt++)
        #pragma unroll
        for (int nt = 0; nt < 8; nt++)
            #pragma unroll
            for (int j = 0; j < 4; j++) acc[mt][nt][j] = 0.f;

    for (int kc = 0; kc < KCHEB; kc++) {
        stage(kc);
        CP_WAIT0();
        __syncthreads();

        #pragma unroll
        for (int ks = 0; ks < 8; ks++) {
            int kb = ks * 16;
            uint32_t a[2][4];
            #pragma unroll
            for (int mt = 0; mt < 2; mt++) {
                const __half* xr = Xs + (wm * 32 + mt * 16 + g) * XS_H + kb;
                a[mt][0] = *(const uint32_t*)(xr + 2 * t);
                a[mt][1] = *(const uint32_t*)(xr + 8 * XS_H + 2 * t);
                a[mt][2] = *(const uint32_t*)(xr + 2 * t + 8);
                a[mt][3] = *(const uint32_t*)(xr + 8 * XS_H + 2 * t + 8);
            }
            #pragma unroll
            for (int nt = 0; nt < 8; nt++) {
                const __half* wr = Ws + (wn * 64 + nt * 8 + g) * XS_H + kb;
                uint32_t b0 = *(const uint32_t*)(wr + 2 * t);
                uint32_t b1 = *(const uint32_t*)(wr + 2 * t + 8);
                mma_f16(acc[0][nt], a[0][0], a[0][1], a[0][2], a[0][3], b0, b1);
                mma_f16(acc[1][nt], a[1][0], a[1][1], a[1][2], a[1][3], b0, b1);
            }
        }
        __syncthreads();
    }

    #pragma unroll
    for (int mt = 0; mt < 2; mt++) {
        int row_lo = row0 + wm * 32 + mt * 16 + g;
        int row_hi = row_lo + 8;
        #pragma unroll
        for (int nt = 0; nt < 8; nt++) {
            int col = wn * 64 + nt * 8 + 2 * t;
            float b0 = g_bsum[col], b1 = g_bsum[col + 1];
            if (row_lo < N_NODES) {
                float2 v = make_float2(acc[mt][nt][0] + b0, acc[mt][nt][1] + b1);
                *(float2*)(out + (size_t)row_lo * C + col) = v;
            }
            if (row_hi < N_NODES) {
                float2 v = make_float2(acc[mt][nt][2] + b0, acc[mt][nt][3] + b1);
                *(float2*)(out + (size_t)row_hi * C + col) = v;
            }
        }
    }
}

// ---------------- launch ----------------
extern "C" void kernel_launch(void* const* d_in, const int* in_sizes, int n_in,
                              void* d_out, int out_size) {
    const float* nodes     = (const float*)d_in[0];
    const float* edges     = (const float*)d_in[1];
    const int*   senders   = (const int*)d_in[2];
    const int*   receivers = (const int*)d_in[3];
    const float* W         = (const float*)d_in[4];
    const float* b_dense   = (const float*)d_in[5];
    const float* bias      = (const float*)d_in[6];
    float* out = (float*)d_out;

    const int NBLK_I = (N_NODES * C / 2 + 255) / 256;
    const int NBLK_S = (N_NODES * 16 + 255) / 256;

    cudaFuncSetAttribute(k_gemm16, cudaFuncAttributeMaxDynamicSharedMemorySize,
                         SMEM_GEMM_BYTES);

    k_init_stats<<<NBLK_I, 256>>>(nodes, edges, senders, W, b_dense, bias);
    k_scan<<<NB_SCAN, 1024>>>();
    k_fill<<<NBLK_E, 256>>>(senders, receivers, edges);

    k_spmv16<<<NBLK_S, 256>>>(0, 0, 1, 0);
    k_spmv16<<<NBLK_S, 256>>>(1, 0, 2, 1);
    k_spmv16<<<NBLK_S, 256>>>(2, 1, 3, 1);
    k_spmv16<<<NBLK_S, 256>>>(3, 2, 4, 1);
    k_spmv16<<<NBLK_S, 256>>>(4, 3, 5, 1);

    k_gemm16<<<NTILES, 256, SMEM_GEMM_BYTES>>>(out);
}